// round 13
// baseline (speedup 1.0000x reference)
#include <cuda_runtime.h>
#include <cuda_bf16.h>
#include <math.h>
#include <stdint.h>

#define B_   4
#define N_   4096
#define D_   64
#define K_   16
#define BN_  (B_*N_)            /* 16384 */
#define XE_SZ  (BN_*D_)         /* 1048576 */
#define EDGE_SZ (BN_*K_)        /* 262144 */

#define CLAMP_XV 1.0e6f
#define GUMBEL_MAX 3.1375f      /* log(-log(1e-10)) = 3.13656, + margin */

#define TPITCH_B 400            /* bytes per tile row: 192 bf16 = 384B + 16 pad */
#define SPITCH   136            /* floats; 136 % 32 == 8 -> conflict-free scan */
#define MTILE    64             /* rows per CTA */

/* 3-level bf16 split of xe: [row][level*64 + d], row-major 384B rows */
__device__ __align__(16) unsigned char xs_g[BN_ * 384];
__device__ float g_sq[BN_];

__device__ __forceinline__ float clampx(float v) {
    return fminf(fmaxf(v, -CLAMP_XV), CLAMP_XV);
}

__device__ __forceinline__ uint32_t smem_u32(const void* p) {
    uint32_t a;
    asm("{ .reg .u64 t; cvta.to.shared.u64 t, %1; cvt.u32.u64 %0, t; }"
        : "=r"(a) : "l"(p));
    return a;
}

__device__ __forceinline__ void cp_async16(uint32_t dst, const void* src) {
    asm volatile("cp.async.cg.shared.global [%0], [%1], 16;"
                 :: "r"(dst), "l"(src));
}
#define CP_COMMIT() asm volatile("cp.async.commit_group;" ::: "memory")
#define CP_WAIT0()  asm volatile("cp.async.wait_group 0;" ::: "memory")

/* ------------------------------------------------------------------ */
/* Kernel 1: xe = clip(clip(x) @ W), row norms, 3-way bf16 split       */
/* ------------------------------------------------------------------ */
__global__ __launch_bounds__(128) void embed_kernel(
    const float* __restrict__ x, const float* __restrict__ W,
    float* __restrict__ xe)
{
    __shared__ float Ws[64*64];
    int tid = threadIdx.x;
    for (int v = tid; v < 1024; v += 128)
        ((float4*)Ws)[v] = ((const float4*)W)[v];
    __syncthreads();

    int r = blockIdx.x * 128 + tid;
    float xv[64];
    const float4* xr = (const float4*)(x + (size_t)r * 64);
    #pragma unroll
    for (int q = 0; q < 16; q++) {
        float4 t = xr[q];
        xv[4*q+0] = clampx(t.x);
        xv[4*q+1] = clampx(t.y);
        xv[4*q+2] = clampx(t.z);
        xv[4*q+3] = clampx(t.w);
    }
    float sq = 0.f;
    float4* outr = (float4*)(xe + (size_t)r * 64);
    unsigned char* xsrow = xs_g + (size_t)r * 384;
    #pragma unroll
    for (int jg = 0; jg < 8; jg++) {
        float acc[8];
        #pragma unroll
        for (int c = 0; c < 8; c++) acc[c] = 0.f;
        #pragma unroll 8
        for (int k = 0; k < 64; k++) {
            float a = xv[k];
            float4 w0 = ((const float4*)Ws)[k*16 + jg*2];
            float4 w1 = ((const float4*)Ws)[k*16 + jg*2 + 1];
            acc[0] = fmaf(a, w0.x, acc[0]);
            acc[1] = fmaf(a, w0.y, acc[1]);
            acc[2] = fmaf(a, w0.z, acc[2]);
            acc[3] = fmaf(a, w0.w, acc[3]);
            acc[4] = fmaf(a, w1.x, acc[4]);
            acc[5] = fmaf(a, w1.y, acc[5]);
            acc[6] = fmaf(a, w1.z, acc[6]);
            acc[7] = fmaf(a, w1.w, acc[7]);
        }
        float e[8];
        #pragma unroll
        for (int c = 0; c < 8; c++) e[c] = clampx(acc[c]);
        outr[jg*2]   = make_float4(e[0], e[1], e[2], e[3]);
        outr[jg*2+1] = make_float4(e[4], e[5], e[6], e[7]);
        unsigned int p0[4], p1[4], p2[4];
        #pragma unroll
        for (int c2 = 0; c2 < 4; c2++) {
            unsigned short lv[3][2];
            #pragma unroll
            for (int u = 0; u < 2; u++) {
                float f = e[c2*2 + u];
                __nv_bfloat16 h0 = __float2bfloat16(f);
                float r1 = f - __bfloat162float(h0);
                __nv_bfloat16 h1 = __float2bfloat16(r1);
                float r2 = r1 - __bfloat162float(h1);
                __nv_bfloat16 h2 = __float2bfloat16(r2);
                lv[0][u] = __bfloat16_as_ushort(h0);
                lv[1][u] = __bfloat16_as_ushort(h1);
                lv[2][u] = __bfloat16_as_ushort(h2);
            }
            p0[c2] = (unsigned)lv[0][0] | ((unsigned)lv[0][1] << 16);
            p1[c2] = (unsigned)lv[1][0] | ((unsigned)lv[1][1] << 16);
            p2[c2] = (unsigned)lv[2][0] | ((unsigned)lv[2][1] << 16);
        }
        *(uint4*)(xsrow +   0 + jg*16) = make_uint4(p0[0], p0[1], p0[2], p0[3]);
        *(uint4*)(xsrow + 128 + jg*16) = make_uint4(p1[0], p1[1], p1[2], p1[3]);
        *(uint4*)(xsrow + 256 + jg*16) = make_uint4(p2[0], p2[1], p2[2], p2[3]);
        #pragma unroll
        for (int c = 0; c < 8; c++) sq = fmaf(e[c], e[c], sq);
    }
    g_sq[r] = sq;
}

/* ------------------------------------------------------------------ */
/* Kernel 2: HMMA distance GEMM (bf16 3-split) + fused Gumbel top-16   */
/* 256 threads, M-tile 64, 2 CTAs/SM for phase overlap                 */
/* ------------------------------------------------------------------ */
#define SM_A   0
#define SM_B   (MTILE*TPITCH_B)               /* 25600 */
#define SM_S   (SM_B + 128*TPITCH_B)          /* 76800, floats [64][SPITCH] */
#define SM_SQB (SM_S + MTILE*SPITCH*4)        /* 111616 */
#define SM_TOT (SM_SQB + 512 + 128)           /* 112256 */

__device__ __forceinline__ void mma_bf16(float* d,
    unsigned a0, unsigned a1, unsigned a2, unsigned a3,
    unsigned b0, unsigned b1)
{
    asm volatile(
        "mma.sync.aligned.m16n8k16.row.col.f32.bf16.bf16.f32 "
        "{%0,%1,%2,%3}, {%4,%5,%6,%7}, {%8,%9}, {%0,%1,%2,%3};"
        : "+f"(d[0]), "+f"(d[1]), "+f"(d[2]), "+f"(d[3])
        : "r"(a0), "r"(a1), "r"(a2), "r"(a3), "r"(b0), "r"(b1));
}

__device__ __forceinline__ void ldmx4(unsigned& r0, unsigned& r1,
                                      unsigned& r2, unsigned& r3, uint32_t a)
{
    asm volatile("ldmatrix.sync.aligned.m8n8.x4.shared.b16 {%0,%1,%2,%3}, [%4];"
                 : "=r"(r0), "=r"(r1), "=r"(r2), "=r"(r3) : "r"(a));
}

__global__ __launch_bounds__(256, 2) void topk_kernel(
    const float* __restrict__ xe, const float* __restrict__ noise,
    const float* __restrict__ temperature, float* __restrict__ out)
{
    extern __shared__ char smem[];
    char*  At  = smem + SM_A;
    char*  Bt  = smem + SM_B;
    float* S   = (float*)(smem + SM_S);
    float* sqB = (float*)(smem + SM_SQB);

    int tid = threadIdx.x;
    int wid = tid >> 5, lane = tid & 31;
    int g = lane >> 2, c = lane & 3;
    int rb = (wid & 3) * 16;          /* warp row band (0..48)  */
    int ch = (wid >> 2) * 64;         /* warp col half (0/64)   */
    int R0 = blockIdx.x * MTILE;
    int batchBase = R0 & ~(N_-1);

    int r = tid >> 2, q = tid & 3;    /* scan + A-fill: row r (0..63), quarter q */
    size_t noiseRow = (size_t)(R0 + r) * N_;
    float sqr = g_sq[R0 + r];

    /* ldmatrix per-lane base addresses */
    uint32_t aAddrBase = smem_u32(At + (rb + (lane & 15))*TPITCH_B)
                         + ((lane >> 4) << 4);
    uint32_t bAddrBase = smem_u32(Bt + (ch + ((lane >> 4) << 3) + (lane & 7))*TPITCH_B)
                         + (((lane >> 3) & 1) << 4);

    /* copy A tile via cp.async: 64 rows x 4 quarters = 256 jobs */
    {
        uint32_t aDst = smem_u32(At + r*TPITCH_B + q*96);
        const char* src = (const char*)(xs_g + (size_t)(R0 + r)*384 + q*96);
        #pragma unroll
        for (int i = 0; i < 6; i++)
            cp_async16(aDst + i*16, src + i*16);
        CP_COMMIT();
    }

    float scale = expf(fminf(fmaxf(*temperature, -5.f), 5.f));
    float invScale = 1.0f / scale;
    const float INF = __int_as_float(0x7f800000);
    float tv[16]; int ti[16];
    #pragma unroll
    for (int s = 0; s < 16; s++) { tv[s] = INF; ti[s] = 0; }
    float thrd = INF;

    for (int jt = 0; jt < 32; jt++) {
        __syncthreads();   /* prev scan done; Bt/sqB reuse safe */
        {
            int J0 = batchBase + jt*128;
            /* 128 rows x 4 quarters = 512 jobs, 2 per thread */
            #pragma unroll
            for (int it = 0; it < 2; it++) {
                int j = tid + 256*it;
                int br = j >> 2, bq = j & 3;
                uint32_t bDst = smem_u32(Bt + br*TPITCH_B + bq*96);
                const char* src = (const char*)(xs_g + (size_t)(J0 + br)*384 + bq*96);
                #pragma unroll
                for (int i = 0; i < 6; i++)
                    cp_async16(bDst + i*16, src + i*16);
            }
            CP_COMMIT();
            if (tid < 128) sqB[tid] = g_sq[J0 + tid];
            CP_WAIT0();
        }
        __syncthreads();

        /* warp m16 x n64, K=192: 6 level-pairs x 4 k-steps x 8 n-tiles */
        float acc[8][4];
        #pragma unroll
        for (int nt = 0; nt < 8; nt++)
            #pragma unroll
            for (int e = 0; e < 4; e++) acc[nt][e] = 0.f;

        const int pa[6] = {0, 0, 128, 128, 0, 256};   /* level*128 byte offsets */
        const int pb[6] = {0, 128, 0, 128, 256, 0};
        #pragma unroll
        for (int p = 0; p < 6; p++) {
            #pragma unroll
            for (int ks = 0; ks < 4; ks++) {
                unsigned a0, a1, a2, a3;
                ldmx4(a0, a1, a2, a3, aAddrBase + pa[p] + ks*32);
                #pragma unroll
                for (int np = 0; np < 4; np++) {
                    unsigned b0, b1, b2, b3;
                    ldmx4(b0, b1, b2, b3,
                          bAddrBase + pb[p] + ks*32 + np*(16*TPITCH_B));
                    mma_bf16(acc[2*np],   a0, a1, a2, a3, b0, b1);
                    mma_bf16(acc[2*np+1], a0, a1, a2, a3, b2, b3);
                }
            }
        }
        /* epilogue: fragments -> S */
        #pragma unroll
        for (int nt = 0; nt < 8; nt++) {
            int col = ch + nt*8 + 2*c;
            *(float2*)(S + (rb + g    )*SPITCH + col) = make_float2(acc[nt][0], acc[nt][1]);
            *(float2*)(S + (rb + g + 8)*SPITCH + col) = make_float2(acc[nt][2], acc[nt][3]);
        }
        __syncthreads();

        /* quad-shared threshold */
        float t15 = tv[15];
        t15 = fminf(t15, __shfl_xor_sync(0xffffffffu, t15, 1));
        t15 = fminf(t15, __shfl_xor_sync(0xffffffffu, t15, 2));
        thrd = fminf(thrd, (t15 + GUMBEL_MAX) * invScale);

        /* scan: 4 threads/row, q-interleaved float4 chunks */
        const float* Srow = S + r*SPITCH;
        #pragma unroll
        for (int jj = 0; jj < 8; jj++) {
            int coff = 16*jj + 4*q;
            float4 dot = *(const float4*)(Srow + coff);
            float4 sb  = *(const float4*)(sqB + coff);
            float d0 = fmaf(dot.x, -2.f, sqr + sb.x);
            float d1 = fmaf(dot.y, -2.f, sqr + sb.y);
            float d2 = fmaf(dot.z, -2.f, sqr + sb.z);
            float d3 = fmaf(dot.w, -2.f, sqr + sb.w);
            float m = fminf(fminf(d0, d1), fminf(d2, d3));
            if (m < thrd) {
                float dd[4] = {d0, d1, d2, d3};
                #pragma unroll
                for (int e = 0; e < 4; e++) {
                    if (dd[e] < thrd) {
                        int jl = jt*128 + coff + e;
                        float de = fminf(fmaxf(dd[e], 0.f), 1e10f);
                        float u = noise[noiseRow + jl];
                        float lq = fmaf(de, scale, -__logf(-__logf(u)));
                        if (lq < tv[15]) {
                            #pragma unroll
                            for (int s = 15; s >= 1; s--) {
                                bool shp  = lq < tv[s-1];
                                bool here = (lq < tv[s]) && !shp;
                                tv[s] = shp ? tv[s-1] : (here ? lq : tv[s]);
                                ti[s] = shp ? ti[s-1] : (here ? jl : ti[s]);
                            }
                            if (lq < tv[0]) { tv[0] = lq; ti[0] = jl; }
                            thrd = (tv[15] + GUMBEL_MAX) * invScale;
                        }
                    }
                }
            }
        }
    }

    __syncthreads();
    /* merge 4 per-row sorted lists (reuse A tile smem) */
    float* vbuf = (float*)(smem + SM_A);          /* [64][64] */
    int*   ibuf = (int*)(smem + SM_A + 16384);    /* [64][64] */
    #pragma unroll
    for (int s = 0; s < 16; s++) {
        vbuf[r*64 + q*16 + s] = tv[s];
        ibuf[r*64 + q*16 + s] = ti[s];
    }
    __syncthreads();
    if (q == 0) {
        const float* vr = vbuf + r*64;
        const int*   ir = ibuf + r*64;
        int p[4] = {0, 16, 32, 48};
        int gr = R0 + r;
        size_t eoff = (size_t)gr * K_;
        #pragma unroll 1
        for (int s = 0; s < 16; s++) {
            float bv = INF; int bi = 0x7fffffff; int bq = 0;
            #pragma unroll
            for (int l = 0; l < 4; l++) {
                float cv = vr[p[l]]; int ci = ir[p[l]];
                if (cv < bv || (cv == bv && ci < bi)) { bv = cv; bi = ci; bq = l; }
            }
            p[bq]++;
            out[XE_SZ + eoff + s]              = (float)gr;
            out[XE_SZ + EDGE_SZ + eoff + s]    = (float)(batchBase + bi);
            out[XE_SZ + 2*EDGE_SZ + eoff + s]  = fminf(fmaxf(bv, -1e10f), 0.f);
        }
    }
}

extern "C" void kernel_launch(void* const* d_in, const int* in_sizes, int n_in,
                              void* d_out, int out_size)
{
    (void)out_size;
    const float *x = nullptr, *W = nullptr, *temp = nullptr, *noise = nullptr;
    for (int i = 0; i < n_in; i++) {
        int s = in_sizes[i];
        if (s == 1)               temp  = (const float*)d_in[i];
        else if (s == D_*D_)      W     = (const float*)d_in[i];
        else if (s == BN_*D_)     x     = (const float*)d_in[i];
        else                      noise = (const float*)d_in[i];
    }
    float* out = (float*)d_out;

    embed_kernel<<<128, 128>>>(x, W, out);

    cudaFuncSetAttribute(topk_kernel,
                         cudaFuncAttributeMaxDynamicSharedMemorySize, SM_TOT);
    topk_kernel<<<BN_/MTILE, 256, SM_TOT>>>(out, noise, temp, out);
}

// round 16
// speedup vs baseline: 1.4384x; 1.4384x over previous
#include <cuda_runtime.h>
#include <cuda_bf16.h>
#include <math.h>
#include <stdint.h>

#define B_   4
#define N_   4096
#define D_   64
#define K_   16
#define BN_  (B_*N_)            /* 16384 */
#define XE_SZ  (BN_*D_)         /* 1048576 */
#define EDGE_SZ (BN_*K_)        /* 262144 */

#define CLAMP_XV 1.0e6f
#define GUMBEL_MAX 3.1375f      /* log(-log(1e-10)) = 3.13656, + margin */

#define TPITCH_B 400            /* bytes per tile row: 192 bf16 = 384B + 16 pad */
#define SPITCH   144            /* floats; conflict-free scan layout */

/* 3-level bf16 split of xe: [row][level*64 + d], row-major 384B rows */
__device__ __align__(16) unsigned char xs_g[BN_ * 384];
__device__ float g_sq[BN_];

__device__ __forceinline__ float clampx(float v) {
    return fminf(fmaxf(v, -CLAMP_XV), CLAMP_XV);
}

__device__ __forceinline__ uint32_t smem_u32(const void* p) {
    uint32_t a;
    asm("{ .reg .u64 t; cvta.to.shared.u64 t, %1; cvt.u32.u64 %0, t; }"
        : "=r"(a) : "l"(p));
    return a;
}

__device__ __forceinline__ void cp_async16(uint32_t dst, const void* src) {
    asm volatile("cp.async.cg.shared.global [%0], [%1], 16;"
                 :: "r"(dst), "l"(src));
}
#define CP_COMMIT() asm volatile("cp.async.commit_group;" ::: "memory")
#define CP_WAIT0()  asm volatile("cp.async.wait_group 0;" ::: "memory")

/* ------------------------------------------------------------------ */
/* Kernel 1: xe = clip(clip(x) @ W), row norms, 3-way bf16 split       */
/* ------------------------------------------------------------------ */
__global__ __launch_bounds__(128) void embed_kernel(
    const float* __restrict__ x, const float* __restrict__ W,
    float* __restrict__ xe)
{
    __shared__ float Ws[64*64];
    int tid = threadIdx.x;
    for (int v = tid; v < 1024; v += 128)
        ((float4*)Ws)[v] = ((const float4*)W)[v];
    __syncthreads();

    int r = blockIdx.x * 128 + tid;
    float xv[64];
    const float4* xr = (const float4*)(x + (size_t)r * 64);
    #pragma unroll
    for (int q = 0; q < 16; q++) {
        float4 t = xr[q];
        xv[4*q+0] = clampx(t.x);
        xv[4*q+1] = clampx(t.y);
        xv[4*q+2] = clampx(t.z);
        xv[4*q+3] = clampx(t.w);
    }
    float sq = 0.f;
    float4* outr = (float4*)(xe + (size_t)r * 64);
    unsigned char* xsrow = xs_g + (size_t)r * 384;
    #pragma unroll
    for (int jg = 0; jg < 8; jg++) {
        float acc[8];
        #pragma unroll
        for (int c = 0; c < 8; c++) acc[c] = 0.f;
        #pragma unroll 8
        for (int k = 0; k < 64; k++) {
            float a = xv[k];
            float4 w0 = ((const float4*)Ws)[k*16 + jg*2];
            float4 w1 = ((const float4*)Ws)[k*16 + jg*2 + 1];
            acc[0] = fmaf(a, w0.x, acc[0]);
            acc[1] = fmaf(a, w0.y, acc[1]);
            acc[2] = fmaf(a, w0.z, acc[2]);
            acc[3] = fmaf(a, w0.w, acc[3]);
            acc[4] = fmaf(a, w1.x, acc[4]);
            acc[5] = fmaf(a, w1.y, acc[5]);
            acc[6] = fmaf(a, w1.z, acc[6]);
            acc[7] = fmaf(a, w1.w, acc[7]);
        }
        float e[8];
        #pragma unroll
        for (int c = 0; c < 8; c++) e[c] = clampx(acc[c]);
        outr[jg*2]   = make_float4(e[0], e[1], e[2], e[3]);
        outr[jg*2+1] = make_float4(e[4], e[5], e[6], e[7]);
        unsigned int p0[4], p1[4], p2[4];
        #pragma unroll
        for (int c2 = 0; c2 < 4; c2++) {
            unsigned short lv[3][2];
            #pragma unroll
            for (int u = 0; u < 2; u++) {
                float f = e[c2*2 + u];
                __nv_bfloat16 h0 = __float2bfloat16(f);
                float r1 = f - __bfloat162float(h0);
                __nv_bfloat16 h1 = __float2bfloat16(r1);
                float r2 = r1 - __bfloat162float(h1);
                __nv_bfloat16 h2 = __float2bfloat16(r2);
                lv[0][u] = __bfloat16_as_ushort(h0);
                lv[1][u] = __bfloat16_as_ushort(h1);
                lv[2][u] = __bfloat16_as_ushort(h2);
            }
            p0[c2] = (unsigned)lv[0][0] | ((unsigned)lv[0][1] << 16);
            p1[c2] = (unsigned)lv[1][0] | ((unsigned)lv[1][1] << 16);
            p2[c2] = (unsigned)lv[2][0] | ((unsigned)lv[2][1] << 16);
        }
        *(uint4*)(xsrow +   0 + jg*16) = make_uint4(p0[0], p0[1], p0[2], p0[3]);
        *(uint4*)(xsrow + 128 + jg*16) = make_uint4(p1[0], p1[1], p1[2], p1[3]);
        *(uint4*)(xsrow + 256 + jg*16) = make_uint4(p2[0], p2[1], p2[2], p2[3]);
        #pragma unroll
        for (int c = 0; c < 8; c++) sq = fmaf(e[c], e[c], sq);
    }
    g_sq[r] = sq;
}

/* ------------------------------------------------------------------ */
/* Kernel 2: HMMA distance GEMM (bf16 3-split, two n32 passes) +       */
/*           fused Gumbel top-16 with min-first insertion              */
/* ------------------------------------------------------------------ */
#define SM_A   0
#define SM_B   (128*TPITCH_B)                 /* 51200 */
#define SM_S   (2*128*TPITCH_B)               /* 102400, floats [128][SPITCH] */
#define SM_SQB (SM_S + 128*SPITCH*4)          /* 176128 */
#define SM_TOT (SM_SQB + 512 + 128)

__device__ __forceinline__ void mma_bf16(float* d,
    unsigned a0, unsigned a1, unsigned a2, unsigned a3,
    unsigned b0, unsigned b1)
{
    asm volatile(
        "mma.sync.aligned.m16n8k16.row.col.f32.bf16.bf16.f32 "
        "{%0,%1,%2,%3}, {%4,%5,%6,%7}, {%8,%9}, {%0,%1,%2,%3};"
        : "+f"(d[0]), "+f"(d[1]), "+f"(d[2]), "+f"(d[3])
        : "r"(a0), "r"(a1), "r"(a2), "r"(a3), "r"(b0), "r"(b1));
}

__device__ __forceinline__ void ldmx4(unsigned& r0, unsigned& r1,
                                      unsigned& r2, unsigned& r3, uint32_t a)
{
    asm volatile("ldmatrix.sync.aligned.m8n8.x4.shared.b16 {%0,%1,%2,%3}, [%4];"
                 : "=r"(r0), "=r"(r1), "=r"(r2), "=r"(r3) : "r"(a));
}

__global__ __launch_bounds__(512, 1) void topk_kernel(
    const float* __restrict__ xe, const float* __restrict__ noise,
    const float* __restrict__ temperature, float* __restrict__ out)
{
    extern __shared__ char smem[];
    char*  At  = smem + SM_A;
    char*  Bt  = smem + SM_B;
    float* S   = (float*)(smem + SM_S);
    float* sqB = (float*)(smem + SM_SQB);

    int tid = threadIdx.x;
    int wid = tid >> 5, lane = tid & 31;
    int g = lane >> 2, c = lane & 3;
    int rb = (wid & 7) * 16;          /* warp row band   */
    int ch = (wid >> 3) * 64;         /* warp col half   */
    int R0 = blockIdx.x * 128;
    int batchBase = R0 & ~(N_-1);

    int r = tid >> 2, q = tid & 3;    /* scan: row r, quarter q */
    size_t noiseRow = (size_t)(R0 + r) * N_;
    float sqr = g_sq[R0 + r];

    /* ldmatrix per-lane base addresses */
    uint32_t aAddrBase = smem_u32(At + (rb + (lane & 15))*TPITCH_B)
                         + ((lane >> 4) << 4);
    uint32_t bAddrBase = smem_u32(Bt + (ch + ((lane >> 4) << 3) + (lane & 7))*TPITCH_B)
                         + (((lane >> 3) & 1) << 4);

    /* fill destinations for this thread (row r, quarter q = 96B) */
    uint32_t aDst = smem_u32(At + r*TPITCH_B + q*96);
    uint32_t bDst = smem_u32(Bt + r*TPITCH_B + q*96);

    /* copy A tile via cp.async */
    {
        const char* src = (const char*)(xs_g + (size_t)(R0 + r)*384 + q*96);
        #pragma unroll
        for (int i = 0; i < 6; i++)
            cp_async16(aDst + i*16, src + i*16);
        CP_COMMIT();
    }

    float scale = expf(fminf(fmaxf(*temperature, -5.f), 5.f));
    float invScale = 1.0f / scale;
    const float INF = __int_as_float(0x7f800000);
    float tv[16]; int ti[16];
    #pragma unroll
    for (int s = 0; s < 16; s++) { tv[s] = INF; ti[s] = 0; }
    float thrd = INF;

    for (int jt = 0; jt < 32; jt++) {
        __syncthreads();   /* prev scan done; Bt/sqB reuse safe */
        {
            int J0 = batchBase + jt*128;
            const char* src = (const char*)(xs_g + (size_t)(J0 + r)*384 + q*96);
            #pragma unroll
            for (int i = 0; i < 6; i++)
                cp_async16(bDst + i*16, src + i*16);
            CP_COMMIT();
            if (tid < 128) sqB[tid] = g_sq[J0 + tid];
            CP_WAIT0();
        }
        __syncthreads();

        /* warp m16 x n64 in TWO n32 passes (16 accumulator regs live) */
        const int pa[6] = {0, 0, 128, 128, 0, 256};   /* level*128 byte offsets */
        const int pb[6] = {0, 128, 0, 128, 256, 0};
        #pragma unroll
        for (int nh = 0; nh < 2; nh++) {
            float acc[4][4];
            #pragma unroll
            for (int nt = 0; nt < 4; nt++)
                #pragma unroll
                for (int e = 0; e < 4; e++) acc[nt][e] = 0.f;

            uint32_t bBase = bAddrBase + nh*(32*TPITCH_B);
            #pragma unroll
            for (int p = 0; p < 6; p++) {
                #pragma unroll
                for (int ks = 0; ks < 4; ks++) {
                    unsigned a0, a1, a2, a3;
                    ldmx4(a0, a1, a2, a3, aAddrBase + pa[p] + ks*32);
                    #pragma unroll
                    for (int np = 0; np < 2; np++) {
                        unsigned b0, b1, b2, b3;
                        ldmx4(b0, b1, b2, b3,
                              bBase + pb[p] + ks*32 + np*(16*TPITCH_B));
                        mma_bf16(acc[2*np],   a0, a1, a2, a3, b0, b1);
                        mma_bf16(acc[2*np+1], a0, a1, a2, a3, b2, b3);
                    }
                }
            }
            #pragma unroll
            for (int nt = 0; nt < 4; nt++) {
                int col = ch + nh*32 + nt*8 + 2*c;
                *(float2*)(S + (rb + g    )*SPITCH + col) = make_float2(acc[nt][0], acc[nt][1]);
                *(float2*)(S + (rb + g + 8)*SPITCH + col) = make_float2(acc[nt][2], acc[nt][3]);
            }
        }
        __syncthreads();

        /* scan: 4 threads/row, q-interleaved float4 chunks */
        const float* Srow = S + r*SPITCH;
        int jbase0 = jt*128;
        #pragma unroll
        for (int jj = 0; jj < 8; jj++) {
            /* per-jj quad-shared threshold (row-wide 16th-best bound) */
            {
                float t15 = tv[15];
                t15 = fminf(t15, __shfl_xor_sync(0xffffffffu, t15, 1));
                t15 = fminf(t15, __shfl_xor_sync(0xffffffffu, t15, 2));
                thrd = fminf(thrd, (t15 + GUMBEL_MAX) * invScale);
            }
            int coff = 16*jj + 4*q;
            float4 dot = *(const float4*)(Srow + coff);
            float4 sb  = *(const float4*)(sqB + coff);
            float d0 = fmaf(dot.x, -2.f, sqr + sb.x);
            float d1 = fmaf(dot.y, -2.f, sqr + sb.y);
            float d2 = fmaf(dot.z, -2.f, sqr + sb.z);
            float d3 = fmaf(dot.w, -2.f, sqr + sb.w);
            float m = fminf(fminf(d0, d1), fminf(d2, d3));
            if (m < thrd) {
                float dd[4] = {d0, d1, d2, d3};
                float lqs[4];
                /* gated Gumbel evaluation for all 4 candidates */
                #pragma unroll
                for (int e = 0; e < 4; e++) {
                    lqs[e] = INF;
                    if (dd[e] < thrd) {
                        float de = fminf(fmaxf(dd[e], 0.f), 1e10f);
                        float u = noise[noiseRow + jbase0 + coff + e];
                        lqs[e] = fmaf(de, scale, -__logf(-__logf(u)));
                    }
                }
                /* min-first insertion: usually one network pass per chunk */
                float bv; int be;
                #pragma unroll 1
                for (;;) {
                    bv = lqs[0]; be = 0;
                    #pragma unroll
                    for (int e = 1; e < 4; e++)
                        if (lqs[e] < bv) { bv = lqs[e]; be = e; }
                    if (!(bv < tv[15])) break;
                    int jl = jbase0 + coff + be;
                    #pragma unroll
                    for (int s = 15; s >= 1; s--) {
                        bool shp  = bv < tv[s-1];
                        bool here = (bv < tv[s]) && !shp;
                        tv[s] = shp ? tv[s-1] : (here ? bv : tv[s]);
                        ti[s] = shp ? ti[s-1] : (here ? jl : ti[s]);
                    }
                    if (bv < tv[0]) { tv[0] = bv; ti[0] = jl; }
                    lqs[be] = INF;
                    thrd = fminf(thrd, (tv[15] + GUMBEL_MAX) * invScale);
                }
            }
        }
    }

    __syncthreads();
    /* merge 4 per-row sorted lists (reuse A/B tile smem) */
    float* vbuf = (float*)(smem + SM_A);          /* [128][64] */
    int*   ibuf = (int*)(smem + SM_A + 32768);    /* [128][64] */
    #pragma unroll
    for (int s = 0; s < 16; s++) {
        vbuf[r*64 + q*16 + s] = tv[s];
        ibuf[r*64 + q*16 + s] = ti[s];
    }
    __syncthreads();
    if (q == 0) {
        const float* vr = vbuf + r*64;
        const int*   ir = ibuf + r*64;
        int p[4] = {0, 16, 32, 48};
        int gr = R0 + r;
        size_t eoff = (size_t)gr * K_;
        #pragma unroll 1
        for (int s = 0; s < 16; s++) {
            float bv = INF; int bi = 0x7fffffff; int bq = 0;
            #pragma unroll
            for (int l = 0; l < 4; l++) {
                float cv = vr[p[l]]; int ci = ir[p[l]];
                if (cv < bv || (cv == bv && ci < bi)) { bv = cv; bi = ci; bq = l; }
            }
            p[bq]++;
            out[XE_SZ + eoff + s]              = (float)gr;
            out[XE_SZ + EDGE_SZ + eoff + s]    = (float)(batchBase + bi);
            out[XE_SZ + 2*EDGE_SZ + eoff + s]  = fminf(fmaxf(bv, -1e10f), 0.f);
        }
    }
}

extern "C" void kernel_launch(void* const* d_in, const int* in_sizes, int n_in,
                              void* d_out, int out_size)
{
    (void)out_size;
    const float *x = nullptr, *W = nullptr, *temp = nullptr, *noise = nullptr;
    for (int i = 0; i < n_in; i++) {
        int s = in_sizes[i];
        if (s == 1)               temp  = (const float*)d_in[i];
        else if (s == D_*D_)      W     = (const float*)d_in[i];
        else if (s == BN_*D_)     x     = (const float*)d_in[i];
        else                      noise = (const float*)d_in[i];
    }
    float* out = (float*)d_out;

    embed_kernel<<<128, 128>>>(x, W, out);

    cudaFuncSetAttribute(topk_kernel,
                         cudaFuncAttributeMaxDynamicSharedMemorySize, SM_TOT);
    topk_kernel<<<128, 512, SM_TOT>>>(out, noise, temp, out);
}

// round 17
// speedup vs baseline: 1.5426x; 1.0725x over previous
#include <cuda_runtime.h>
#include <cuda_bf16.h>
#include <math.h>
#include <stdint.h>

#define B_   4
#define N_   4096
#define D_   64
#define K_   16
#define BN_  (B_*N_)            /* 16384 */
#define XE_SZ  (BN_*D_)         /* 1048576 */
#define EDGE_SZ (BN_*K_)        /* 262144 */

#define CLAMP_XV 1.0e6f
#define GUMBEL_MAX 3.1375f      /* log(-log(1e-10)) = 3.13656, + margin */

#define TPITCH_B 400            /* bytes per tile row: 192 bf16 = 384B + 16 pad */
#define SPITCH   136            /* floats; 136%32==8 -> conflict-free scan+epilogue */

/* 3-level bf16 split of xe: [row][level*64 + d], row-major 384B rows */
__device__ __align__(16) unsigned char xs_g[BN_ * 384];
__device__ float g_sq[BN_];

__device__ __forceinline__ float clampx(float v) {
    return fminf(fmaxf(v, -CLAMP_XV), CLAMP_XV);
}

__device__ __forceinline__ uint32_t smem_u32(const void* p) {
    uint32_t a;
    asm("{ .reg .u64 t; cvta.to.shared.u64 t, %1; cvt.u32.u64 %0, t; }"
        : "=r"(a) : "l"(p));
    return a;
}

__device__ __forceinline__ void cp_async16(uint32_t dst, const void* src) {
    asm volatile("cp.async.cg.shared.global [%0], [%1], 16;"
                 :: "r"(dst), "l"(src));
}
#define CP_COMMIT() asm volatile("cp.async.commit_group;" ::: "memory")
#define CP_WAIT0()  asm volatile("cp.async.wait_group 0;" ::: "memory")
#define BAR_SYNC(id, cnt)   asm volatile("bar.sync %0, %1;"   :: "r"(id), "r"(cnt) : "memory")
#define BAR_ARRIVE(id, cnt) asm volatile("bar.arrive %0, %1;" :: "r"(id), "r"(cnt) : "memory")
#define MEMBAR_CTA() asm volatile("membar.cta;" ::: "memory")

/* named barrier ids */
#define BID_PROD   1
#define BID_FULL0  2
#define BID_FULL1  3
#define BID_FREE0  4
#define BID_FREE1  5
#define BID_CONS   6

/* ------------------------------------------------------------------ */
/* Kernel 1: xe = clip(clip(x) @ W), row norms, 3-way bf16 split       */
/* ------------------------------------------------------------------ */
__global__ __launch_bounds__(128) void embed_kernel(
    const float* __restrict__ x, const float* __restrict__ W,
    float* __restrict__ xe)
{
    __shared__ float Ws[64*64];
    int tid = threadIdx.x;
    for (int v = tid; v < 1024; v += 128)
        ((float4*)Ws)[v] = ((const float4*)W)[v];
    __syncthreads();

    int r = blockIdx.x * 128 + tid;
    float xv[64];
    const float4* xr = (const float4*)(x + (size_t)r * 64);
    #pragma unroll
    for (int q = 0; q < 16; q++) {
        float4 t = xr[q];
        xv[4*q+0] = clampx(t.x);
        xv[4*q+1] = clampx(t.y);
        xv[4*q+2] = clampx(t.z);
        xv[4*q+3] = clampx(t.w);
    }
    float sq = 0.f;
    float4* outr = (float4*)(xe + (size_t)r * 64);
    unsigned char* xsrow = xs_g + (size_t)r * 384;
    #pragma unroll
    for (int jg = 0; jg < 8; jg++) {
        float acc[8];
        #pragma unroll
        for (int c = 0; c < 8; c++) acc[c] = 0.f;
        #pragma unroll 8
        for (int k = 0; k < 64; k++) {
            float a = xv[k];
            float4 w0 = ((const float4*)Ws)[k*16 + jg*2];
            float4 w1 = ((const float4*)Ws)[k*16 + jg*2 + 1];
            acc[0] = fmaf(a, w0.x, acc[0]);
            acc[1] = fmaf(a, w0.y, acc[1]);
            acc[2] = fmaf(a, w0.z, acc[2]);
            acc[3] = fmaf(a, w0.w, acc[3]);
            acc[4] = fmaf(a, w1.x, acc[4]);
            acc[5] = fmaf(a, w1.y, acc[5]);
            acc[6] = fmaf(a, w1.z, acc[6]);
            acc[7] = fmaf(a, w1.w, acc[7]);
        }
        float e[8];
        #pragma unroll
        for (int c = 0; c < 8; c++) e[c] = clampx(acc[c]);
        outr[jg*2]   = make_float4(e[0], e[1], e[2], e[3]);
        outr[jg*2+1] = make_float4(e[4], e[5], e[6], e[7]);
        unsigned int p0[4], p1[4], p2[4];
        #pragma unroll
        for (int c2 = 0; c2 < 4; c2++) {
            unsigned short lv[3][2];
            #pragma unroll
            for (int u = 0; u < 2; u++) {
                float f = e[c2*2 + u];
                __nv_bfloat16 h0 = __float2bfloat16(f);
                float r1 = f - __bfloat162float(h0);
                __nv_bfloat16 h1 = __float2bfloat16(r1);
                float r2 = r1 - __bfloat162float(h1);
                __nv_bfloat16 h2 = __float2bfloat16(r2);
                lv[0][u] = __bfloat16_as_ushort(h0);
                lv[1][u] = __bfloat16_as_ushort(h1);
                lv[2][u] = __bfloat16_as_ushort(h2);
            }
            p0[c2] = (unsigned)lv[0][0] | ((unsigned)lv[0][1] << 16);
            p1[c2] = (unsigned)lv[1][0] | ((unsigned)lv[1][1] << 16);
            p2[c2] = (unsigned)lv[2][0] | ((unsigned)lv[2][1] << 16);
        }
        *(uint4*)(xsrow +   0 + jg*16) = make_uint4(p0[0], p0[1], p0[2], p0[3]);
        *(uint4*)(xsrow + 128 + jg*16) = make_uint4(p1[0], p1[1], p1[2], p1[3]);
        *(uint4*)(xsrow + 256 + jg*16) = make_uint4(p2[0], p2[1], p2[2], p2[3]);
        #pragma unroll
        for (int c = 0; c < 8; c++) sq = fmaf(e[c], e[c], sq);
    }
    g_sq[r] = sq;
}

/* ------------------------------------------------------------------ */
/* Kernel 2: warp-specialized HMMA GEMM producer / Gumbel-topk         */
/*           consumer with double-buffered S                           */
/* ------------------------------------------------------------------ */
#define SM_B    0                              /* Bt: 128*400 = 51200 */
#define SM_S0   (128*TPITCH_B)                 /* 51200, 128*136*4 = 69632 */
#define SM_S1   (SM_S0 + 128*SPITCH*4)         /* 120832 */
#define SM_SQB  (SM_S1 + 128*SPITCH*4)         /* 190464: float[2][128] */
#define SM_TOT  (SM_SQB + 1024 + 128)

__device__ __forceinline__ void mma_bf16(float* d,
    unsigned a0, unsigned a1, unsigned a2, unsigned a3,
    unsigned b0, unsigned b1)
{
    asm volatile(
        "mma.sync.aligned.m16n8k16.row.col.f32.bf16.bf16.f32 "
        "{%0,%1,%2,%3}, {%4,%5,%6,%7}, {%8,%9}, {%0,%1,%2,%3};"
        : "+f"(d[0]), "+f"(d[1]), "+f"(d[2]), "+f"(d[3])
        : "r"(a0), "r"(a1), "r"(a2), "r"(a3), "r"(b0), "r"(b1));
}

__device__ __forceinline__ void ldmx4(unsigned& r0, unsigned& r1,
                                      unsigned& r2, unsigned& r3, uint32_t a)
{
    asm volatile("ldmatrix.sync.aligned.m8n8.x4.shared.b16 {%0,%1,%2,%3}, [%4];"
                 : "=r"(r0), "=r"(r1), "=r"(r2), "=r"(r3) : "r"(a));
}

__global__ __launch_bounds__(512, 1) void topk_kernel(
    const float* __restrict__ xe, const float* __restrict__ noise,
    const float* __restrict__ temperature, float* __restrict__ out)
{
    extern __shared__ char smem[];
    char*  Bt  = smem + SM_B;
    float* sqBB = (float*)(smem + SM_SQB);    /* [2][128] */

    int tid = threadIdx.x;
    int wid = tid >> 5, lane = tid & 31;
    int R0 = blockIdx.x * 128;
    int batchBase = R0 & ~(N_-1);

    /* ---- stage A into Bt region, producers hoist A-fragments ---- */
    {
        int r = tid >> 2, q = tid & 3;
        uint32_t dst = smem_u32(Bt + r*TPITCH_B + q*96);
        const char* src = (const char*)(xs_g + (size_t)(R0 + r)*384 + q*96);
        #pragma unroll
        for (int i = 0; i < 6; i++)
            cp_async16(dst + i*16, src + i*16);
        CP_COMMIT(); CP_WAIT0();
    }
    __syncthreads();

    if (wid < 8) {
        /* =================== PRODUCER (GEMM) =================== */
        int ptid = tid;                       /* 0..255 */
        int rb = wid * 16;
        uint32_t aAddrBase = smem_u32(Bt + (rb + (lane & 15))*TPITCH_B)
                             + ((lane >> 4) << 4);
        unsigned af[3][4][4];
        #pragma unroll
        for (int lvl = 0; lvl < 3; lvl++)
            #pragma unroll
            for (int ks = 0; ks < 4; ks++)
                ldmx4(af[lvl][ks][0], af[lvl][ks][1],
                      af[lvl][ks][2], af[lvl][ks][3],
                      aAddrBase + lvl*128 + ks*32);
        __syncthreads();                      /* A read done; Bt reusable */

        uint32_t bAddrBase = smem_u32(Bt + (((lane >> 4) << 3) + (lane & 7))*TPITCH_B)
                             + (((lane >> 3) & 1) << 4);
        /* B fill job: row = ptid>>1, half = ptid&1 (192B each) */
        int fr = ptid >> 1, fh = ptid & 1;
        uint32_t bDst = smem_u32(Bt + fr*TPITCH_B + fh*192);
        const char* bSrcBase = (const char*)(xs_g) + (size_t)fh*192 + (size_t)fr*384;

        /* fill tile 0 + preload sq */
        {
            const char* src = bSrcBase + (size_t)batchBase*384;
            #pragma unroll
            for (int i = 0; i < 12; i++)
                cp_async16(bDst + i*16, src + i*16);
            CP_COMMIT();
        }
        float sqv = (ptid < 128) ? g_sq[batchBase + ptid] : 0.f;

        const int la[6]  = {0, 0, 1, 1, 0, 2};
        const int lbo[6] = {0, 128, 0, 128, 256, 0};

        for (int t = 0; t < 32; t++) {
            int buf = t & 1;
            if (t >= 2) BAR_SYNC(buf ? BID_FREE1 : BID_FREE0, 512);
            if (ptid < 128) sqBB[buf*128 + ptid] = sqv;
            CP_WAIT0();
            BAR_SYNC(BID_PROD, 256);          /* Bt(t) fully filled */

            float* S = (float*)(smem + (buf ? SM_S1 : SM_S0));
            int g = lane >> 2, c = lane & 3;
            #pragma unroll
            for (int nh = 0; nh < 2; nh++) {
                float acc[8][4];
                #pragma unroll
                for (int nt = 0; nt < 8; nt++)
                    #pragma unroll
                    for (int e = 0; e < 4; e++) acc[nt][e] = 0.f;
                uint32_t bBase = bAddrBase + nh*(64*TPITCH_B);
                #pragma unroll
                for (int p = 0; p < 6; p++) {
                    #pragma unroll
                    for (int ks = 0; ks < 4; ks++) {
                        const unsigned* a = af[la[p]][ks];
                        #pragma unroll
                        for (int np = 0; np < 4; np++) {
                            unsigned b0, b1, b2, b3;
                            ldmx4(b0, b1, b2, b3,
                                  bBase + lbo[p] + ks*32 + np*(16*TPITCH_B));
                            mma_bf16(acc[2*np],   a[0], a[1], a[2], a[3], b0, b1);
                            mma_bf16(acc[2*np+1], a[0], a[1], a[2], a[3], b2, b3);
                        }
                    }
                }
                #pragma unroll
                for (int nt = 0; nt < 8; nt++) {
                    int col = nh*64 + nt*8 + 2*c;
                    *(float2*)(S + (rb + g    )*SPITCH + col) = make_float2(acc[nt][0], acc[nt][1]);
                    *(float2*)(S + (rb + g + 8)*SPITCH + col) = make_float2(acc[nt][2], acc[nt][3]);
                }
            }
            MEMBAR_CTA();
            BAR_ARRIVE(buf ? BID_FULL1 : BID_FULL0, 512);
            BAR_SYNC(BID_PROD, 256);          /* all producers done reading Bt */

            if (t + 1 < 32) {
                int J1 = batchBase + (t+1)*128;
                const char* src = bSrcBase + (size_t)J1*384;
                #pragma unroll
                for (int i = 0; i < 12; i++)
                    cp_async16(bDst + i*16, src + i*16);
                CP_COMMIT();
                if (ptid < 128) sqv = g_sq[J1 + ptid];
            }
        }
        /* producers done */
    } else {
        /* =================== CONSUMER (scan) =================== */
        __syncthreads();                      /* match producer's 2nd sync */
        int ctid = tid - 256;                 /* 0..255 */
        int r = ctid >> 1, h = ctid & 1;      /* row, half */
        size_t noiseRow = (size_t)(R0 + r) * N_;
        float sqr = g_sq[R0 + r];

        float scale = expf(fminf(fmaxf(*temperature, -5.f), 5.f));
        float invScale = 1.0f / scale;
        const float INF = __int_as_float(0x7f800000);
        float tv[16]; int ti[16];
        #pragma unroll
        for (int s = 0; s < 16; s++) { tv[s] = INF; ti[s] = 0; }
        float thrd = INF;

        for (int t = 0; t < 32; t++) {
            int buf = t & 1;
            BAR_SYNC(buf ? BID_FULL1 : BID_FULL0, 512);
            const float* Srow = (const float*)(smem + (buf ? SM_S1 : SM_S0)) + r*SPITCH;
            const float* sqB = sqBB + buf*128;
            int jbase0 = t*128;
            #pragma unroll
            for (int jj = 0; jj < 16; jj++) {
                {   /* pair-shared threshold */
                    float t15 = fminf(tv[15], __shfl_xor_sync(0xffffffffu, tv[15], 1));
                    thrd = fminf(thrd, (t15 + GUMBEL_MAX) * invScale);
                }
                int coff = h*4 + jj*8;
                float4 dot = *(const float4*)(Srow + coff);
                float4 sb  = *(const float4*)(sqB + coff);
                float d0 = fmaf(dot.x, -2.f, sqr + sb.x);
                float d1 = fmaf(dot.y, -2.f, sqr + sb.y);
                float d2 = fmaf(dot.z, -2.f, sqr + sb.z);
                float d3 = fmaf(dot.w, -2.f, sqr + sb.w);
                float m = fminf(fminf(d0, d1), fminf(d2, d3));
                if (m < thrd) {
                    float dd[4] = {d0, d1, d2, d3};
                    float lqs[4];
                    #pragma unroll
                    for (int e = 0; e < 4; e++) {
                        lqs[e] = INF;
                        if (dd[e] < thrd) {
                            float de = fminf(fmaxf(dd[e], 0.f), 1e10f);
                            float u = noise[noiseRow + jbase0 + coff + e];
                            lqs[e] = fmaf(de, scale, -__logf(-__logf(u)));
                        }
                    }
                    float bv; int be;
                    #pragma unroll 1
                    for (;;) {
                        bv = lqs[0]; be = 0;
                        #pragma unroll
                        for (int e = 1; e < 4; e++)
                            if (lqs[e] < bv) { bv = lqs[e]; be = e; }
                        if (!(bv < tv[15])) break;
                        int jl = jbase0 + coff + be;
                        #pragma unroll
                        for (int s = 15; s >= 1; s--) {
                            bool shp  = bv < tv[s-1];
                            bool here = (bv < tv[s]) && !shp;
                            tv[s] = shp ? tv[s-1] : (here ? bv : tv[s]);
                            ti[s] = shp ? ti[s-1] : (here ? jl : ti[s]);
                        }
                        if (bv < tv[0]) { tv[0] = bv; ti[0] = jl; }
                        lqs[be] = INF;
                        thrd = fminf(thrd, (tv[15] + GUMBEL_MAX) * invScale);
                    }
                }
            }
            BAR_ARRIVE(buf ? BID_FREE1 : BID_FREE0, 512);
        }

        /* merge 2 per-row sorted lists: dump into S0 region (idle) */
        float* vbuf = (float*)(smem + SM_S0);         /* [128][32] */
        int*   ibuf = (int*)(smem + SM_S0 + 16384);   /* [128][32] */
        #pragma unroll
        for (int s = 0; s < 16; s++) {
            vbuf[r*32 + h*16 + s] = tv[s];
            ibuf[r*32 + h*16 + s] = ti[s];
        }
        BAR_SYNC(BID_CONS, 256);
        if (h == 0) {
            const float* v0 = vbuf + r*32; const float* v1 = v0 + 16;
            const int*   i0 = ibuf + r*32; const int*   i1 = i0 + 16;
            int p0 = 0, p1 = 0;
            int gr = R0 + r;
            size_t eoff = (size_t)gr * K_;
            #pragma unroll 1
            for (int s = 0; s < 16; s++) {
                float a = v0[p0], b = v1[p1];
                int   ia = i0[p0], ib = i1[p1];
                bool take0 = (a < b) || (a == b && ia < ib);
                float val = take0 ? a : b;
                int   idx = take0 ? ia : ib;
                if (take0) p0++; else p1++;
                out[XE_SZ + eoff + s]              = (float)gr;
                out[XE_SZ + EDGE_SZ + eoff + s]    = (float)(batchBase + idx);
                out[XE_SZ + 2*EDGE_SZ + eoff + s]  = fminf(fmaxf(val, -1e10f), 0.f);
            }
        }
    }
}

extern "C" void kernel_launch(void* const* d_in, const int* in_sizes, int n_in,
                              void* d_out, int out_size)
{
    (void)out_size;
    const float *x = nullptr, *W = nullptr, *temp = nullptr, *noise = nullptr;
    for (int i = 0; i < n_in; i++) {
        int s = in_sizes[i];
        if (s == 1)               temp  = (const float*)d_in[i];
        else if (s == D_*D_)      W     = (const float*)d_in[i];
        else if (s == BN_*D_)     x     = (const float*)d_in[i];
        else                      noise = (const float*)d_in[i];
    }
    float* out = (float*)d_out;

    embed_kernel<<<128, 128>>>(x, W, out);

    cudaFuncSetAttribute(topk_kernel,
                         cudaFuncAttributeMaxDynamicSharedMemorySize, SM_TOT);
    topk_kernel<<<128, 512, SM_TOT>>>(out, noise, temp, out);
}